// round 9
// baseline (speedup 1.0000x reference)
#include <cuda_runtime.h>
#include <float.h>

#define BB 4096
#define NN 2048
#define THREADS 256              // 8 warps/CTA
#define NCTAS 512                // 4096 warps total = one warp per batch row; ONE wave
#define NWORKERS (NCTAS - 1)     // blocks 1..511 signal; block 0 watches

// Per-row fused weighted loss (0.5*n1 + 0.25*n2 + 0.25*n3). Fixed-order final sum.
__device__ float g_rowloss[BB];
__device__ unsigned int g_count = 0;

// Per-(warp,pair) NRMSE: warp lanes stream one 2048-float row of (o,t).
__device__ __forceinline__ float pair_nrmse(const float* __restrict__ o,
                                            const float* __restrict__ t,
                                            int b, int l) {
    const float4* __restrict__ o4 = reinterpret_cast<const float4*>(o + (size_t)b * NN);
    const float4* __restrict__ t4 = reinterpret_cast<const float4*>(t + (size_t)b * NN);

    float ssq = 0.0f, mx = -FLT_MAX, mn = FLT_MAX;

    #pragma unroll
    for (int c = 0; c < 4; c++) {
        const int base = l + c * 128;
        float4 a0 = o4[base];
        float4 a1 = o4[base + 32];
        float4 a2 = o4[base + 64];
        float4 a3 = o4[base + 96];
        float4 b0 = t4[base];
        float4 b1 = t4[base + 32];
        float4 b2 = t4[base + 64];
        float4 b3 = t4[base + 96];

        float d;
        d = a0.x - b0.x; ssq = fmaf(d, d, ssq); mx = fmaxf(mx, b0.x); mn = fminf(mn, b0.x);
        d = a0.y - b0.y; ssq = fmaf(d, d, ssq); mx = fmaxf(mx, b0.y); mn = fminf(mn, b0.y);
        d = a0.z - b0.z; ssq = fmaf(d, d, ssq); mx = fmaxf(mx, b0.z); mn = fminf(mn, b0.z);
        d = a0.w - b0.w; ssq = fmaf(d, d, ssq); mx = fmaxf(mx, b0.w); mn = fminf(mn, b0.w);
        d = a1.x - b1.x; ssq = fmaf(d, d, ssq); mx = fmaxf(mx, b1.x); mn = fminf(mn, b1.x);
        d = a1.y - b1.y; ssq = fmaf(d, d, ssq); mx = fmaxf(mx, b1.y); mn = fminf(mn, b1.y);
        d = a1.z - b1.z; ssq = fmaf(d, d, ssq); mx = fmaxf(mx, b1.z); mn = fminf(mn, b1.z);
        d = a1.w - b1.w; ssq = fmaf(d, d, ssq); mx = fmaxf(mx, b1.w); mn = fminf(mn, b1.w);
        d = a2.x - b2.x; ssq = fmaf(d, d, ssq); mx = fmaxf(mx, b2.x); mn = fminf(mn, b2.x);
        d = a2.y - b2.y; ssq = fmaf(d, d, ssq); mx = fmaxf(mx, b2.y); mn = fminf(mn, b2.y);
        d = a2.z - b2.z; ssq = fmaf(d, d, ssq); mx = fmaxf(mx, b2.z); mn = fminf(mn, b2.z);
        d = a2.w - b2.w; ssq = fmaf(d, d, ssq); mx = fmaxf(mx, b2.w); mn = fminf(mn, b2.w);
        d = a3.x - b3.x; ssq = fmaf(d, d, ssq); mx = fmaxf(mx, b3.x); mn = fminf(mn, b3.x);
        d = a3.y - b3.y; ssq = fmaf(d, d, ssq); mx = fmaxf(mx, b3.y); mn = fminf(mn, b3.y);
        d = a3.z - b3.z; ssq = fmaf(d, d, ssq); mx = fmaxf(mx, b3.z); mn = fminf(mn, b3.z);
        d = a3.w - b3.w; ssq = fmaf(d, d, ssq); mx = fmaxf(mx, b3.w); mn = fminf(mn, b3.w);
    }

    #pragma unroll
    for (int s = 16; s > 0; s >>= 1) {
        ssq += __shfl_xor_sync(0xFFFFFFFFu, ssq, s);
        mx   = fmaxf(mx, __shfl_xor_sync(0xFFFFFFFFu, mx, s));
        mn   = fminf(mn, __shfl_xor_sync(0xFFFFFFFFu, mn, s));
    }
    return sqrtf(ssq * (1.0f / NN)) / (mx - mn);
}

__global__ __launch_bounds__(THREADS)
void wnrmse_persistent_kernel(const float* __restrict__ o1, const float* __restrict__ t1,
                              const float* __restrict__ o2, const float* __restrict__ t2,
                              const float* __restrict__ o3, const float* __restrict__ t3,
                              float* __restrict__ out) {
    const int tid = threadIdx.x;
    const int l = tid & 31;
    const int b = blockIdx.x * 8 + (tid >> 5);   // one warp per batch row, 0..4095

    // ---- Streaming: each warp does all 3 pairs of its row. No barriers. ----
    float loss = 0.50f * pair_nrmse(o1, t1, b, l)
               + 0.25f * pair_nrmse(o2, t2, b, l)
               + 0.25f * pair_nrmse(o3, t3, b, l);
    if (l == 0) g_rowloss[b] = loss;

    __syncthreads();   // one barrier per CTA: all 8 rows' stores done

    if (blockIdx.x != 0) {
        // Fire-and-forget release signal (511 total; never blocks the CTA).
        if (tid == 0)
            asm volatile("red.release.gpu.global.add.u32 [%0], %1;"
                         :: "l"(&g_count), "r"(1u) : "memory");
        return;
    }

    // ---- Block 0: watcher + final fixed-order reduction ----
    if (tid == 0) {
        unsigned int c;
        do {
            asm volatile("ld.acquire.gpu.global.u32 %0, [%1];"
                         : "=r"(c) : "l"(&g_count) : "memory");
            if (c == (unsigned)NWORKERS) break;
            __nanosleep(100);
        } while (true);
    }
    __syncthreads();

    // 4096 floats = 1024 float4; 256 threads -> 4 each, L2-hot, front-batched.
    const float4* __restrict__ p4 = reinterpret_cast<const float4*>(g_rowloss);
    float4 v0 = p4[tid];
    float4 v1 = p4[tid + 256];
    float4 v2 = p4[tid + 512];
    float4 v3 = p4[tid + 768];
    float s = ((v0.x + v0.y) + (v0.z + v0.w))
            + ((v1.x + v1.y) + (v1.z + v1.w))
            + ((v2.x + v2.y) + (v2.z + v2.w))
            + ((v3.x + v3.y) + (v3.z + v3.w));

    #pragma unroll
    for (int sh = 16; sh > 0; sh >>= 1)
        s += __shfl_xor_sync(0xFFFFFFFFu, s, sh);

    __shared__ float s_fin[8];
    const int w = tid >> 5;
    if (l == 0) s_fin[w] = s;
    __syncthreads();
    if (tid == 0) {
        float a = ((s_fin[0] + s_fin[1]) + (s_fin[2] + s_fin[3]))
                + ((s_fin[4] + s_fin[5]) + (s_fin[6] + s_fin[7]));
        out[0] = a * (1.0f / BB);
        g_count = 0;   // reset for next graph replay (all 511 arrivals observed)
    }
}

extern "C" void kernel_launch(void* const* d_in, const int* in_sizes, int n_in,
                              void* d_out, int out_size) {
    const float* o1 = (const float*)d_in[0];
    const float* t1 = (const float*)d_in[1];
    const float* o2 = (const float*)d_in[2];
    const float* t2 = (const float*)d_in[3];
    const float* o3 = (const float*)d_in[4];
    const float* t3 = (const float*)d_in[5];
    float* out = (float*)d_out;

    wnrmse_persistent_kernel<<<NCTAS, THREADS>>>(o1, t1, o2, t2, o3, t3, out);
}

// round 11
// speedup vs baseline: 1.0676x; 1.0676x over previous
#include <cuda_runtime.h>
#include <float.h>

#define BB 4096
#define NN 2048
#define NPAIR 3
#define ROW_THREADS 256
#define RED_THREADS 1024

// Per-(pair,row) weighted contributions. Deterministic fixed-order final sum.
__device__ float g_partials[NPAIR * BB];

// 128-bit streaming load (evict-first): data is read exactly once.
__device__ __forceinline__ float4 ldg128_cs(const float4* __restrict__ p) {
    float4 v;
    asm volatile("ld.global.cs.v4.f32 {%0,%1,%2,%3}, [%4];"
                 : "=f"(v.x), "=f"(v.y), "=f"(v.z), "=f"(v.w)
                 : "l"(p));
    return v;
}

__global__ __launch_bounds__(ROW_THREADS)
void wnrmse_row_kernel(const float* __restrict__ o1, const float* __restrict__ t1,
                       const float* __restrict__ o2, const float* __restrict__ t2,
                       const float* __restrict__ o3, const float* __restrict__ t3) {
    const int b = blockIdx.x;   // batch row
    const int p = blockIdx.y;   // pair index
    const int tid = threadIdx.x;

    const float* o = (p == 0) ? o1 : ((p == 1) ? o2 : o3);
    const float* t = (p == 0) ? t1 : ((p == 1) ? t2 : t3);

    const float4* __restrict__ o4 = reinterpret_cast<const float4*>(o + (size_t)b * NN);
    const float4* __restrict__ t4 = reinterpret_cast<const float4*>(t + (size_t)b * NN);

    // 2048 floats = 512 float4; 256 threads -> 2 float4 each. Front-batch all 4 loads.
    float4 ov0 = ldg128_cs(o4 + tid);
    float4 tv0 = ldg128_cs(t4 + tid);
    float4 ov1 = ldg128_cs(o4 + tid + ROW_THREADS);
    float4 tv1 = ldg128_cs(t4 + tid + ROW_THREADS);

    float ssq = 0.0f, tmax = -FLT_MAX, tmin = FLT_MAX;
    {
        float d;
        d = ov0.x - tv0.x; ssq = fmaf(d, d, ssq); tmax = fmaxf(tmax, tv0.x); tmin = fminf(tmin, tv0.x);
        d = ov0.y - tv0.y; ssq = fmaf(d, d, ssq); tmax = fmaxf(tmax, tv0.y); tmin = fminf(tmin, tv0.y);
        d = ov0.z - tv0.z; ssq = fmaf(d, d, ssq); tmax = fmaxf(tmax, tv0.z); tmin = fminf(tmin, tv0.z);
        d = ov0.w - tv0.w; ssq = fmaf(d, d, ssq); tmax = fmaxf(tmax, tv0.w); tmin = fminf(tmin, tv0.w);
        d = ov1.x - tv1.x; ssq = fmaf(d, d, ssq); tmax = fmaxf(tmax, tv1.x); tmin = fminf(tmin, tv1.x);
        d = ov1.y - tv1.y; ssq = fmaf(d, d, ssq); tmax = fmaxf(tmax, tv1.y); tmin = fminf(tmin, tv1.y);
        d = ov1.z - tv1.z; ssq = fmaf(d, d, ssq); tmax = fmaxf(tmax, tv1.z); tmin = fminf(tmin, tv1.z);
        d = ov1.w - tv1.w; ssq = fmaf(d, d, ssq); tmax = fmaxf(tmax, tv1.w); tmin = fminf(tmin, tv1.w);
    }

    // Intra-warp reduce
    #pragma unroll
    for (int s = 16; s > 0; s >>= 1) {
        ssq  += __shfl_xor_sync(0xFFFFFFFFu, ssq,  s);
        tmax  = fmaxf(tmax, __shfl_xor_sync(0xFFFFFFFFu, tmax, s));
        tmin  = fminf(tmin, __shfl_xor_sync(0xFFFFFFFFu, tmin, s));
    }

    // Cross-warp reduce (8 warps)
    __shared__ float s_ssq[8], s_max[8], s_min[8];
    const int w = tid >> 5, l = tid & 31;
    if (l == 0) { s_ssq[w] = ssq; s_max[w] = tmax; s_min[w] = tmin; }
    __syncthreads();

    if (tid == 0) {
        float a  = ((s_ssq[0] + s_ssq[1]) + (s_ssq[2] + s_ssq[3]))
                 + ((s_ssq[4] + s_ssq[5]) + (s_ssq[6] + s_ssq[7]));
        float mx = fmaxf(fmaxf(fmaxf(s_max[0], s_max[1]), fmaxf(s_max[2], s_max[3])),
                         fmaxf(fmaxf(s_max[4], s_max[5]), fmaxf(s_max[6], s_max[7])));
        float mn = fminf(fminf(fminf(s_min[0], s_min[1]), fminf(s_min[2], s_min[3])),
                         fminf(fminf(s_min[4], s_min[5]), fminf(s_min[6], s_min[7])));
        const float wgt = (p == 0) ? 0.5f : 0.25f;
        g_partials[p * BB + b] = wgt * sqrtf(a * (1.0f / NN)) / (mx - mn);
    }
}

// Tail (PDL): overlaps its launch front-end with the primary's drain.
__global__ __launch_bounds__(RED_THREADS)
void wnrmse_reduce_kernel(float* __restrict__ out) {
    cudaGridDependencySynchronize();

    const int tid = threadIdx.x;
    const float4* __restrict__ p4 = reinterpret_cast<const float4*>(g_partials);

    float4 v0 = p4[tid];
    float4 v1 = p4[tid + RED_THREADS];
    float4 v2 = p4[tid + 2 * RED_THREADS];

    float s = ((v0.x + v0.y) + (v0.z + v0.w))
            + ((v1.x + v1.y) + (v1.z + v1.w))
            + ((v2.x + v2.y) + (v2.z + v2.w));

    #pragma unroll
    for (int sh = 16; sh > 0; sh >>= 1)
        s += __shfl_xor_sync(0xFFFFFFFFu, s, sh);

    __shared__ float s_part[32];
    const int w = tid >> 5, l = tid & 31;
    if (l == 0) s_part[w] = s;
    __syncthreads();
    if (w == 0) {
        float a = s_part[l];   // exactly 32 warps
        #pragma unroll
        for (int sh = 16; sh > 0; sh >>= 1)
            a += __shfl_xor_sync(0xFFFFFFFFu, a, sh);
        if (l == 0) out[0] = a * (1.0f / BB);
    }
}

extern "C" void kernel_launch(void* const* d_in, const int* in_sizes, int n_in,
                              void* d_out, int out_size) {
    const float* o1 = (const float*)d_in[0];
    const float* t1 = (const float*)d_in[1];
    const float* o2 = (const float*)d_in[2];
    const float* t2 = (const float*)d_in[3];
    const float* o3 = (const float*)d_in[4];
    const float* t3 = (const float*)d_in[5];
    float* out = (float*)d_out;

    dim3 grid(BB, NPAIR);
    wnrmse_row_kernel<<<grid, ROW_THREADS>>>(o1, t1, o2, t2, o3, t3);

    cudaLaunchConfig_t cfg = {};
    cfg.gridDim = dim3(1, 1, 1);
    cfg.blockDim = dim3(RED_THREADS, 1, 1);
    cfg.dynamicSmemBytes = 0;
    cfg.stream = 0;
    cudaLaunchAttribute attrs[1];
    attrs[0].id = cudaLaunchAttributeProgrammaticStreamSerialization;
    attrs[0].val.programmaticStreamSerializationAllowed = 1;
    cfg.attrs = attrs;
    cfg.numAttrs = 1;
    cudaLaunchKernelEx(&cfg, wnrmse_reduce_kernel, out);
}